// round 1
// baseline (speedup 1.0000x reference)
#include <cuda_runtime.h>
#include <cuda_bf16.h>

#define MM 9
#define DD 128
#define NT 28          // examples per block
#define THREADS 128

// shared memory layout (floats)
#define SW_OFF   0                    // W[m]: 128 rows x (128+4 pad) = 16896
#define SF_OFF   16896                // f tile: 28 x 128 = 3584
#define SFS_OFF  20480                // fsum:   28 x 128 = 3584
#define SG_OFF   24064                // g: 28 x 9 x 128 = 32256
#define SMEM_FLOATS 56320
#define SMEM_BYTES (SMEM_FLOATS * 4)  // 225280 B  (< 227 KB max dyn smem)

__device__ __forceinline__ constexpr int pidx(int j, int k) {
    // index of pair (j,k), j<k, in row-major upper-triangle order
    return j * 8 - j * (j - 1) / 2 + (k - j - 1);
}

__global__ void __launch_bounds__(THREADS, 1)
inter_rm_fused(const float* __restrict__ F,   // [N, 9, 128]
               const float* __restrict__ Wg,  // [9, 128, 128]
               float* __restrict__ out,       // [N, 128]
               int N)
{
    extern __shared__ float sm[];
    float*  sW  = sm + SW_OFF;
    float*  sG  = sm + SG_OFF;
    float4* sW4 = reinterpret_cast<float4*>(sW);
    float4* sF4 = reinterpret_cast<float4*>(sm + SF_OFF);
    float4* sFs4= reinterpret_cast<float4*>(sm + SFS_OFF);
    const float4* Fg4 = reinterpret_cast<const float4*>(F);
    const float4* Wg4 = reinterpret_cast<const float4*>(Wg);

    const int tid  = threadIdx.x;
    const int lane = tid & 31;
    const int warp = tid >> 5;     // 0..3
    const int eg   = lane;         // e-lane: handles e = eg, eg+32, eg+64, eg+96
    const int nb   = warp * 7;     // n micro-tile base within block tile
    const int n0   = blockIdx.x * NT;

    // ---------------- Phase 1: g[m] = relu(f[:,m,:] @ W[m]^T), 9 slot GEMMs ----
    for (int m = 0; m < MM; ++m) {
        __syncthreads();   // protect sW/sF reuse across m iterations

        // load W[m] (128x128 fp32) into smem, rows padded to 132 floats
        #pragma unroll
        for (int r = 0; r < 32; ++r) {
            int s = tid + r * THREADS;          // 0..4095 float4 slots
            int e = s >> 5, q = s & 31;
            sW4[e * 33 + q] = Wg4[m * 4096 + s];
        }
        // load f tile for slot m, accumulate fsum
        #pragma unroll
        for (int r = 0; r < 7; ++r) {
            int s = tid + r * THREADS;          // 0..895
            int i = s >> 5, q = s & 31;
            int n = n0 + i;
            float4 v = make_float4(0.f, 0.f, 0.f, 0.f);
            if (n < N) v = Fg4[(n * MM + m) * 32 + q];
            sF4[s] = v;
            if (m == 0) {
                sFs4[s] = v;
            } else {
                float4 t = sFs4[s];
                t.x += v.x; t.y += v.y; t.z += v.z; t.w += v.w;
                sFs4[s] = t;
            }
        }
        __syncthreads();

        float acc[7][4];
        #pragma unroll
        for (int i = 0; i < 7; ++i) {
            acc[i][0] = 0.f; acc[i][1] = 0.f; acc[i][2] = 0.f; acc[i][3] = 0.f;
        }

        #pragma unroll 4
        for (int kk = 0; kk < 32; ++kk) {
            float4 w0 = sW4[(eg     ) * 33 + kk];
            float4 w1 = sW4[(eg + 32) * 33 + kk];
            float4 w2 = sW4[(eg + 64) * 33 + kk];
            float4 w3 = sW4[(eg + 96) * 33 + kk];
            #pragma unroll
            for (int i = 0; i < 7; ++i) {
                float4 fv = sF4[(nb + i) * 32 + kk];   // warp-uniform: broadcast
                acc[i][0] = fmaf(fv.x, w0.x, acc[i][0]);
                acc[i][0] = fmaf(fv.y, w0.y, acc[i][0]);
                acc[i][0] = fmaf(fv.z, w0.z, acc[i][0]);
                acc[i][0] = fmaf(fv.w, w0.w, acc[i][0]);
                acc[i][1] = fmaf(fv.x, w1.x, acc[i][1]);
                acc[i][1] = fmaf(fv.y, w1.y, acc[i][1]);
                acc[i][1] = fmaf(fv.z, w1.z, acc[i][1]);
                acc[i][1] = fmaf(fv.w, w1.w, acc[i][1]);
                acc[i][2] = fmaf(fv.x, w2.x, acc[i][2]);
                acc[i][2] = fmaf(fv.y, w2.y, acc[i][2]);
                acc[i][2] = fmaf(fv.z, w2.z, acc[i][2]);
                acc[i][2] = fmaf(fv.w, w2.w, acc[i][2]);
                acc[i][3] = fmaf(fv.x, w3.x, acc[i][3]);
                acc[i][3] = fmaf(fv.y, w3.y, acc[i][3]);
                acc[i][3] = fmaf(fv.z, w3.z, acc[i][3]);
                acc[i][3] = fmaf(fv.w, w3.w, acc[i][3]);
            }
        }
        // relu + write g to smem (consumed after the barrier below / next-m sync)
        #pragma unroll
        for (int i = 0; i < 7; ++i) {
            float* gr = sG + ((nb + i) * MM + m) * DD;
            gr[eg     ] = fmaxf(acc[i][0], 0.f);
            gr[eg + 32] = fmaxf(acc[i][1], 0.f);
            gr[eg + 64] = fmaxf(acc[i][2], 0.f);
            gr[eg + 96] = fmaxf(acc[i][3], 0.f);
        }
    }
    __syncthreads();

    // ---------------- Phase 2: edges colsum + output --------------------------
    const float4* sG4 = reinterpret_cast<const float4*>(sG);
    float4* out4 = reinterpret_cast<float4*>(out);

    for (int i = warp; i < NT; i += 4) {
        const int n = n0 + i;

        float4 gm[MM];
        #pragma unroll
        for (int m = 0; m < MM; ++m)
            gm[m] = sG4[(i * MM + m) * 32 + lane];

        // per-lane partial squared distances over this lane's 4 dims
        float sp[36];
        #pragma unroll
        for (int j = 0; j < MM; ++j) {
            #pragma unroll
            for (int k = j + 1; k < MM; ++k) {
                float dx = gm[j].x - gm[k].x;
                float dy = gm[j].y - gm[k].y;
                float dz = gm[j].z - gm[k].z;
                float dw = gm[j].w - gm[k].w;
                float s  = dx * dx;
                s = fmaf(dy, dy, s);
                s = fmaf(dz, dz, s);
                s = fmaf(dw, dw, s);
                sp[pidx(j, k)] = s;
            }
        }

        // butterfly-reduce each pair; pair p parked on lane (p&31), slot A/B
        float mysA = 1.f, mysB = 1.f;
        #pragma unroll
        for (int p = 0; p < 36; ++p) {
            float v = sp[p];
            v += __shfl_xor_sync(0xffffffffu, v, 16);
            v += __shfl_xor_sync(0xffffffffu, v, 8);
            v += __shfl_xor_sync(0xffffffffu, v, 4);
            v += __shfl_xor_sync(0xffffffffu, v, 2);
            v += __shfl_xor_sync(0xffffffffu, v, 1);
            if (p < 32) { if (lane == p)      mysA = v; }
            else        { if (lane == p - 32) mysB = v; }
        }

        // edge = tanh(sqrt(s)) (0 when s<=0), via 1 - 2/(exp(2x)+1)
        float xA = (mysA > 0.f) ? mysA * __frsqrt_rn(mysA) : 0.f;
        float xB = (mysB > 0.f) ? mysB * __frsqrt_rn(mysB) : 0.f;
        float eA = 1.f - __fdividef(2.f, __expf(2.f * xA) + 1.f);
        float eB = 1.f - __fdividef(2.f, __expf(2.f * xB) + 1.f);

        // column sums cs[k] = sum_j edges[j][k], gathered via shfl
        float cs[MM];
        #pragma unroll
        for (int k = 0; k < MM; ++k) {
            float a = 0.f;
            #pragma unroll
            for (int j = 0; j < MM; ++j) {
                if (j == k) continue;
                const int p = (j < k) ? pidx(j, k) : pidx(k, j);
                float e = (p < 32) ? __shfl_sync(0xffffffffu, eA, p)
                                   : __shfl_sync(0xffffffffu, eB, p - 32);
                a += e;
            }
            cs[k] = a;
        }

        // y = 0.5 * (fsum + sum_k cs[k] * g[k])
        float4 fs = sFs4[i * 32 + lane];
        float ux = 0.f, uy = 0.f, uz = 0.f, uw = 0.f;
        #pragma unroll
        for (int k = 0; k < MM; ++k) {
            ux = fmaf(cs[k], gm[k].x, ux);
            uy = fmaf(cs[k], gm[k].y, uy);
            uz = fmaf(cs[k], gm[k].z, uz);
            uw = fmaf(cs[k], gm[k].w, uw);
        }
        if (n < N) {
            float4 o;
            o.x = 0.5f * (fs.x + ux);
            o.y = 0.5f * (fs.y + uy);
            o.z = 0.5f * (fs.z + uz);
            o.w = 0.5f * (fs.w + uw);
            out4[n * 32 + lane] = o;
        }
    }
}

extern "C" void kernel_launch(void* const* d_in, const int* in_sizes, int n_in,
                              void* d_out, int out_size) {
    const float* F = (const float*)d_in[0];   // f [N,9,128] fp32
    const float* W = (const float*)d_in[1];   // W [9,128,128] fp32
    float* out = (float*)d_out;               // y [N,128] fp32
    const int N = in_sizes[0] / (MM * DD);

    cudaFuncSetAttribute(inter_rm_fused,
                         cudaFuncAttributeMaxDynamicSharedMemorySize, SMEM_BYTES);
    const int grid = (N + NT - 1) / NT;
    inter_rm_fused<<<grid, THREADS, SMEM_BYTES>>>(F, W, out, N);
}